// round 16
// baseline (speedup 1.0000x reference)
#include <cuda_runtime.h>
#include <cstdint>
#include <cstddef>

// ---------------------------------------------------------------------------
// BitNet b1.58 fused MLP on GB300 (sm_103; legacy mma.sync IMMA path).
// Hybrid GEMM: warps 8-15 do a 128x128 IMMA tile, warps 0-7 do 128x64 extra
// columns via __dp4a (LDS.64 feeds).
// R16: BK 64->128 (two 64B k-halves per stage), 3 stages -- halves the
// __syncthreads cadence that drains the tensor pipe.
// ---------------------------------------------------------------------------

#define EPSF 1e-5f

constexpr int T_TOK = 4096;   // B*S
constexpr int HDIM  = 4096;
constexpr int IDIM  = 11008;
constexpr long WELEMS = (long)IDIM * HDIM;

constexpr int BN_T   = 128;   // tensor cols per CTA
constexpr int BN_D   = 64;    // dp4a cols per CTA
constexpr int BN_ALL = BN_T + BN_D;   // 192

// ------------------------- device scratch ----------------------------------
__device__ __align__(128) int8_t d_wgq[WELEMS];
__device__ __align__(128) int8_t d_wuq[WELEMS];
__device__ __align__(128) int8_t d_wdq8[WELEMS];
__device__ __align__(128) int8_t d_xq[(long)T_TOK * HDIM];
__device__ __align__(128) int8_t d_hq[(long)T_TOK * IDIM];
__device__ __align__(128) float  d_gbuf[(long)T_TOK * IDIM];
__device__ __align__(128) float  d_ubuf[(long)T_TOK * IDIM];
__device__ float  d_xs[T_TOK];
__device__ float  d_hs[T_TOK];
__device__ double d_wsum[3];

// ------------------------- helpers -----------------------------------------
__device__ __forceinline__ unsigned smem_u32(const void* p) {
    return (unsigned)__cvta_generic_to_shared(p);
}
__device__ __forceinline__ unsigned swz64(unsigned off) {   // 64B-row swizzle
    return off ^ ((off >> 3) & 0x30);
}
__device__ __forceinline__ void cp16(unsigned saddr, const void* g) {
    asm volatile("cp.async.cg.shared.global [%0], [%1], 16;\n" :: "r"(saddr), "l"(g));
}
__device__ __forceinline__ void ldsm4(unsigned* r, unsigned addr) {
    asm volatile("ldmatrix.sync.aligned.m8n8.x4.shared.b16 {%0,%1,%2,%3}, [%4];"
                 : "=r"(r[0]), "=r"(r[1]), "=r"(r[2]), "=r"(r[3]) : "r"(addr));
}
__device__ __forceinline__ void mma_s8(int* c, const unsigned* a, const unsigned* b) {
    asm volatile(
        "mma.sync.aligned.m16n8k32.row.col.s32.s8.s8.s32 "
        "{%0,%1,%2,%3}, {%4,%5,%6,%7}, {%8,%9}, {%0,%1,%2,%3};\n"
        : "+r"(c[0]), "+r"(c[1]), "+r"(c[2]), "+r"(c[3])
        : "r"(a[0]), "r"(a[1]), "r"(a[2]), "r"(a[3]), "r"(b[0]), "r"(b[1]));
}
__device__ __forceinline__ float wdeq_of(int idx) {
    return (float)fmax(d_wsum[idx] / (double)WELEMS, (double)EPSF);
}

__device__ __forceinline__ float blockMaxF(float v, float* red) {
    #pragma unroll
    for (int o = 16; o > 0; o >>= 1)
        v = fmaxf(v, __shfl_down_sync(0xffffffffu, v, o));
    int wid = threadIdx.x >> 5;
    if ((threadIdx.x & 31) == 0) red[wid] = v;
    __syncthreads();
    if (threadIdx.x < 8) {
        v = red[threadIdx.x];
        #pragma unroll
        for (int o = 4; o > 0; o >>= 1)
            v = fmaxf(v, __shfl_down_sync(0xffu, v, o));
        if (threadIdx.x == 0) red[0] = v;
    }
    __syncthreads();
    return red[0];
}

// ------------------------- small kernels -----------------------------------
__global__ void quantx_kernel(const float* __restrict__ x) {
    if (blockIdx.x == 0 && threadIdx.x < 3) d_wsum[threadIdx.x] = 0.0;
    __shared__ float red[8];
    const int t = blockIdx.x;
    const float4* xr = (const float4*)(x + (size_t)t * HDIM);
    float4 v[4];
    float m = 0.f;
    #pragma unroll
    for (int j = 0; j < 4; ++j) {
        v[j] = xr[threadIdx.x + j * 256];
        m = fmaxf(m, fmaxf(fmaxf(fabsf(v[j].x), fabsf(v[j].y)),
                           fmaxf(fabsf(v[j].z), fabsf(v[j].w))));
    }
    float amax = blockMaxF(m, red);
    float cmax = fmaxf(amax, EPSF);
    float sc = 127.0f / cmax;
    if (threadIdx.x == 0) d_xs[t] = cmax / 127.0f;
    char4* q4 = (char4*)(d_xq + (size_t)t * HDIM);
    #pragma unroll
    for (int j = 0; j < 4; ++j) {
        char4 c;
        c.x = (signed char)fminf(fmaxf(rintf(v[j].x * sc), -128.f), 127.f);
        c.y = (signed char)fminf(fmaxf(rintf(v[j].y * sc), -128.f), 127.f);
        c.z = (signed char)fminf(fmaxf(rintf(v[j].z * sc), -128.f), 127.f);
        c.w = (signed char)fminf(fmaxf(rintf(v[j].w * sc), -128.f), 127.f);
        q4[threadIdx.x + j * 256] = c;
    }
}

__global__ void absmean3_kernel(const float* __restrict__ w0,
                                const float* __restrict__ w1,
                                const float* __restrict__ w2) {
    const int idx = blockIdx.z;
    const float* w = (idx == 0) ? w0 : (idx == 1) ? w1 : w2;
    const size_t n4 = (size_t)WELEMS / 4;
    const float4* w4 = (const float4*)w;
    float a0 = 0.f, a1 = 0.f, a2 = 0.f, a3 = 0.f;
    for (size_t i = (size_t)blockIdx.x * blockDim.x + threadIdx.x; i < n4;
         i += (size_t)gridDim.x * blockDim.x) {
        float4 v = w4[i];
        a0 += fabsf(v.x); a1 += fabsf(v.y); a2 += fabsf(v.z); a3 += fabsf(v.w);
    }
    double local = ((double)a0 + (double)a1) + ((double)a2 + (double)a3);
    #pragma unroll
    for (int o = 16; o > 0; o >>= 1)
        local += __shfl_down_sync(0xffffffffu, local, o);
    __shared__ double red[8];
    int wid = threadIdx.x >> 5;
    if ((threadIdx.x & 31) == 0) red[wid] = local;
    __syncthreads();
    if (threadIdx.x < 8) {
        local = red[threadIdx.x];
        #pragma unroll
        for (int o = 4; o > 0; o >>= 1)
            local += __shfl_down_sync(0xffu, local, o);
        if (threadIdx.x == 0) atomicAdd(&d_wsum[idx], local);
    }
}

__global__ void quantw3_kernel(const float* __restrict__ w0,
                               const float* __restrict__ w1,
                               const float* __restrict__ w2) {
    const int idx = blockIdx.z;
    const float* w = (idx == 0) ? w0 : (idx == 1) ? w1 : w2;
    int8_t* q = (idx == 0) ? d_wgq : (idx == 1) ? d_wuq : d_wdq8;
    const float s = 1.0f / wdeq_of(idx);
    const size_t n4 = (size_t)WELEMS / 4;
    const float4* w4 = (const float4*)w;
    char4* q4 = (char4*)q;
    for (size_t i = (size_t)blockIdx.x * blockDim.x + threadIdx.x; i < n4;
         i += (size_t)gridDim.x * blockDim.x) {
        float4 v = w4[i];
        char4 c;
        c.x = (signed char)fminf(fmaxf(rintf(v.x * s), -1.f), 1.f);
        c.y = (signed char)fminf(fmaxf(rintf(v.y * s), -1.f), 1.f);
        c.z = (signed char)fminf(fmaxf(rintf(v.z * s), -1.f), 1.f);
        c.w = (signed char)fminf(fmaxf(rintf(v.w * s), -1.f), 1.f);
        q4[i] = c;
    }
}

__global__ void combine_quanth_kernel() {
    __shared__ float sh[IDIM];
    __shared__ float red[8];
    const int t = blockIdx.x;
    const float4* gr = (const float4*)(d_gbuf + (size_t)t * IDIM);
    const float4* ur = (const float4*)(d_ubuf + (size_t)t * IDIM);
    float4* sh4 = (float4*)sh;
    float m = 0.f;
    for (int i = threadIdx.x; i < IDIM / 4; i += 256) {
        float4 gv = gr[i], uv = ur[i], h;
        float r;
        r = fmaxf(gv.x, 0.f); h.x = r * r * uv.x;
        r = fmaxf(gv.y, 0.f); h.y = r * r * uv.y;
        r = fmaxf(gv.z, 0.f); h.z = r * r * uv.z;
        r = fmaxf(gv.w, 0.f); h.w = r * r * uv.w;
        sh4[i] = h;
        m = fmaxf(m, fmaxf(fmaxf(fabsf(h.x), fabsf(h.y)),
                           fmaxf(fabsf(h.z), fabsf(h.w))));
    }
    float amax = blockMaxF(m, red);
    float cmax = fmaxf(amax, EPSF);
    float sc = 127.0f / cmax;
    if (threadIdx.x == 0) d_hs[t] = cmax / 127.0f;
    __syncthreads();
    char4* q4 = (char4*)(d_hq + (size_t)t * IDIM);
    for (int i = threadIdx.x; i < IDIM / 4; i += 256) {
        float4 h = sh4[i];
        char4 c;
        c.x = (signed char)fminf(fmaxf(rintf(h.x * sc), -128.f), 127.f);
        c.y = (signed char)fminf(fmaxf(rintf(h.y * sc), -128.f), 127.f);
        c.z = (signed char)fminf(fmaxf(rintf(h.z * sc), -128.f), 127.f);
        c.w = (signed char)fminf(fmaxf(rintf(h.w * sc), -128.f), 127.f);
        q4[i] = c;
    }
}

// ------------------------- hybrid int8 GEMM --------------------------------
// C[M=4096, NDIM] = A[M, KDIM] (s8, K-major) x B[NDIM, KDIM]^T (s8)
// Per CTA: cols n0..n0+127 via IMMA (warps 8-15), n0+128..n0+191 via dp4a
// (warps 0-7, LDS.64). BK=128 per chunk, stored as two 64B k-halves:
// stage = A0(8K) A1(8K) B0(12K) B1(12K) = 40KB, 3 stages.
template <int NDIM, int KDIM, int MODE>
__global__ __launch_bounds__(512, 1) void gemm_s8_kernel(float* __restrict__ out_arg) {
    constexpr int BK = 128;
    constexpr int STAGE_B = 40960;
    constexpr int OFF_B = 16384;              // B half0 offset within stage
    constexpr int AHALF = 8192;               // A half stride
    constexpr int BHALF = 12288;              // B half stride
    constexpr int KT = KDIM / BK;
    extern __shared__ int8_t smem[];
    const unsigned sbase = smem_u32(smem);

    const int8_t* A;
    const int8_t* Bm;
    float* outp;
    const float* ascale;
    int wsel;
    if (MODE == 0) {
        A = d_xq; ascale = d_xs;
        if (blockIdx.z == 0) { Bm = d_wgq; outp = d_gbuf; wsel = 0; }
        else                 { Bm = d_wuq; outp = d_ubuf; wsel = 1; }
    } else {
        A = d_hq; ascale = d_hs; Bm = d_wdq8; outp = out_arg; wsel = 2;
    }

    const int tid = threadIdx.x;
    const int m0 = blockIdx.y * 128, n0 = blockIdx.x * BN_ALL;
    const int wid = tid >> 5, lane = tid & 31;

    auto load_stage = [&](int kt) {
        if (kt < KT) {
            const unsigned sS = sbase + (kt % 3) * STAGE_B;
            const int k0 = kt * BK;
            // A: 128 rows x 2 halves x 4 segs = 1024 units, 2 per thread
            #pragma unroll
            for (int i = 0; i < 2; ++i) {
                int u = tid + i * 512;           // 0..1023
                int row = (u >> 3);              // 0..127
                int s8 = u & 7;                  // half*4 + seg
                int hh = s8 >> 2, seg = s8 & 3;
                cp16(sS + hh * AHALF + swz64(row * 64 + seg * 16),
                     A + (size_t)(m0 + row) * KDIM + k0 + hh * 64 + seg * 16);
            }
            // B: 192 rows x 2 halves x 4 segs = 1536 units, 3 per thread
            #pragma unroll
            for (int i = 0; i < 3; ++i) {
                int v = tid + i * 512;           // 0..1535
                int row = (v >> 3);              // 0..191
                int s8 = v & 7;
                int hh = s8 >> 2, seg = s8 & 3;
                int rb = n0 + row;
                if (rb >= NDIM) rb = NDIM - 1;
                cp16(sS + OFF_B + hh * BHALF + swz64(row * 64 + seg * 16),
                     Bm + (size_t)rb * KDIM + k0 + hh * 64 + seg * 16);
            }
        }
        asm volatile("cp.async.commit_group;\n");
    };

    load_stage(0); load_stage(1);

    if (wid >= 8) {
        // ======== tensor warps (wid 8-15, HIGH priority): 128x128 IMMA =====
        const int wt = wid - 8;
        const int wm = (wt & 1) * 64, wn = (wt >> 1) * 32;
        const int arow = lane & 15, aks = (lane >> 4) * 16;
        const int brow = (lane & 7) + ((lane >> 4) & 1) * 8;
        const int bks  = ((lane >> 3) & 1) * 16;

        int acc[4][4][4];
        #pragma unroll
        for (int mi = 0; mi < 4; ++mi)
            #pragma unroll
            for (int ni = 0; ni < 4; ++ni)
                #pragma unroll
                for (int k = 0; k < 4; ++k) acc[mi][ni][k] = 0;

        for (int kt = 0; kt < KT; ++kt) {
            asm volatile("cp.async.wait_group 1;\n");
            __syncthreads();
            const unsigned sS = sbase + (kt % 3) * STAGE_B;
            #pragma unroll
            for (int hh = 0; hh < 2; ++hh) {
                const unsigned sA = sS + hh * AHALF;
                const unsigned sB = sS + OFF_B + hh * BHALF;
                #pragma unroll
                for (int kk = 0; kk < 64; kk += 32) {
                    unsigned a[4][4], b[2][4];
                    #pragma unroll
                    for (int mi = 0; mi < 4; ++mi)
                        ldsm4(a[mi], sA + swz64((wm + mi * 16 + arow) * 64 + kk + aks));
                    #pragma unroll
                    for (int np = 0; np < 2; ++np)
                        ldsm4(b[np], sB + swz64((wn + np * 16 + brow) * 64 + kk + bks));
                    #pragma unroll
                    for (int mi = 0; mi < 4; ++mi)
                        #pragma unroll
                        for (int ni = 0; ni < 4; ++ni)
                            mma_s8(acc[mi][ni], a[mi], &b[ni >> 1][(ni & 1) * 2]);
                }
            }
            load_stage(kt + 2);
        }

        const float wsc = wdeq_of(wsel);
        const int g = lane >> 2, tg = lane & 3;
        #pragma unroll
        for (int mi = 0; mi < 4; ++mi) {
            int r0 = m0 + wm + mi * 16 + g;
            int r1 = r0 + 8;
            float s0 = ascale[r0] * wsc;
            float s1 = ascale[r1] * wsc;
            #pragma unroll
            for (int ni = 0; ni < 4; ++ni) {
                int c = n0 + wn + ni * 8 + tg * 2;
                if (c < NDIM) {
                    float2 v0 = make_float2(acc[mi][ni][0] * s0, acc[mi][ni][1] * s0);
                    float2 v1 = make_float2(acc[mi][ni][2] * s1, acc[mi][ni][3] * s1);
                    *(float2*)(outp + (size_t)r0 * NDIM + c) = v0;
                    *(float2*)(outp + (size_t)r1 * NDIM + c) = v1;
                }
            }
        }
    } else {
        // ==== dp4a warps (wid 0-7, LOW priority): 128x64 cols, LDS.64 ======
        const int wd = wid;
        const int wm2 = (wd & 1) * 64;
        const int wn2 = BN_T + (wd >> 1) * 16;
        const int rg = lane >> 2;
        const int cg = lane & 3;

        int acc2[8][4];
        #pragma unroll
        for (int i = 0; i < 8; ++i)
            #pragma unroll
            for (int j = 0; j < 4; ++j) acc2[i][j] = 0;

        for (int kt = 0; kt < KT; ++kt) {
            asm volatile("cp.async.wait_group 1;\n");
            __syncthreads();
            const int8_t* sS = smem + (kt % 3) * STAGE_B;
            #pragma unroll
            for (int hh = 0; hh < 2; ++hh) {
                const int8_t* sAp = sS + hh * AHALF;
                const int8_t* sBp = sS + OFF_B + hh * BHALF;
                #pragma unroll
                for (int kw8 = 0; kw8 < 8; ++kw8) {
                    int2 a2[8], b2[4];
                    #pragma unroll
                    for (int i = 0; i < 8; ++i)
                        a2[i] = *(const int2*)(sAp +
                            swz64((wm2 + rg + 8 * i) * 64 + kw8 * 8));
                    #pragma unroll
                    for (int j = 0; j < 4; ++j)
                        b2[j] = *(const int2*)(sBp +
                            swz64((wn2 + cg + 4 * j) * 64 + kw8 * 8));
                    #pragma unroll
                    for (int i = 0; i < 8; ++i)
                        #pragma unroll
                        for (int j = 0; j < 4; ++j) {
                            int s = acc2[i][j];
                            s = __dp4a(a2[i].x, b2[j].x, s);
                            s = __dp4a(a2[i].y, b2[j].y, s);
                            acc2[i][j] = s;
                        }
                }
            }
            load_stage(kt + 2);
        }

        const float wsc = wdeq_of(wsel);
        #pragma unroll
        for (int i = 0; i < 8; ++i) {
            int r = m0 + wm2 + rg + 8 * i;
            float s = ascale[r] * wsc;
            #pragma unroll
            for (int j = 0; j < 4; ++j) {
                int c = n0 + wn2 + cg + 4 * j;
                if (c < NDIM)
                    outp[(size_t)r * NDIM + c] = acc2[i][j] * s;
            }
        }
    }
}

// ------------------------- launch ------------------------------------------
extern "C" void kernel_launch(void* const* d_in, const int* in_sizes, int n_in,
                              void* d_out, int out_size) {
    const float* x      = (const float*)d_in[0];
    const float* w_gate = (const float*)d_in[1];
    const float* w_up   = (const float*)d_in[2];
    const float* w_down = (const float*)d_in[3];
    float* out = (float*)d_out;

    constexpr int GSMEM = 3 * 40960;   // 122880 B dynamic

    cudaFuncSetAttribute(gemm_s8_kernel<IDIM, HDIM, 0>,
                         cudaFuncAttributeMaxDynamicSharedMemorySize, GSMEM);
    cudaFuncSetAttribute(gemm_s8_kernel<HDIM, IDIM, 1>,
                         cudaFuncAttributeMaxDynamicSharedMemorySize, GSMEM);

    // 1: x quant (+ wsum zero)
    quantx_kernel<<<T_TOK, 256>>>(x);
    // 2: weight abs-mean
    absmean3_kernel<<<dim3(592, 1, 3), 256>>>(w_gate, w_up, w_down);
    // 3: weight ternary quant
    quantw3_kernel<<<dim3(592, 1, 3), 256>>>(w_gate, w_up, w_down);
    // 4: gate+up GEMM (hybrid)  <-- ncu capture lands here
    gemm_s8_kernel<IDIM, HDIM, 0>
        <<<dim3((IDIM + BN_ALL - 1) / BN_ALL, T_TOK / 128, 2), 512, GSMEM>>>(nullptr);
    // 5: gating + h quant
    combine_quanth_kernel<<<T_TOK, 256>>>();
    // 6: down GEMM -> output (hybrid)
    gemm_s8_kernel<HDIM, IDIM, 1>
        <<<dim3((HDIM + BN_ALL - 1) / BN_ALL, T_TOK / 128, 1), 512, GSMEM>>>(out);
}

// round 17
// speedup vs baseline: 1.1364x; 1.1364x over previous
#include <cuda_runtime.h>
#include <cstdint>
#include <cstddef>

// ---------------------------------------------------------------------------
// BitNet b1.58 fused MLP on GB300 (sm_103; legacy mma.sync IMMA path).
// Hybrid GEMM: warps 8-15 do a 128x128 IMMA tile (tensor pipe), warps 0-7 do
// 128x128 extra columns via __dp4a (8x8 outputs/thread, LDS.64 feeds).
// R17: dp4a tile widened 64->128 cols via register reuse (ratio 8 dp4a/LDS).
// BN_ALL=256 divides 11008 and 4096 exactly -> no edge guards.
// ---------------------------------------------------------------------------

#define EPSF 1e-5f

constexpr int T_TOK = 4096;   // B*S
constexpr int HDIM  = 4096;
constexpr int IDIM  = 11008;
constexpr long WELEMS = (long)IDIM * HDIM;

constexpr int BN_T   = 128;   // tensor cols per CTA
constexpr int BN_D   = 128;   // dp4a cols per CTA
constexpr int BN_ALL = BN_T + BN_D;   // 256

// ------------------------- device scratch ----------------------------------
__device__ __align__(128) int8_t d_wgq[WELEMS];
__device__ __align__(128) int8_t d_wuq[WELEMS];
__device__ __align__(128) int8_t d_wdq8[WELEMS];
__device__ __align__(128) int8_t d_xq[(long)T_TOK * HDIM];
__device__ __align__(128) int8_t d_hq[(long)T_TOK * IDIM];
__device__ __align__(128) float  d_gbuf[(long)T_TOK * IDIM];
__device__ __align__(128) float  d_ubuf[(long)T_TOK * IDIM];
__device__ float  d_xs[T_TOK];
__device__ float  d_hs[T_TOK];
__device__ double d_wsum[3];

// ------------------------- helpers -----------------------------------------
__device__ __forceinline__ unsigned smem_u32(const void* p) {
    return (unsigned)__cvta_generic_to_shared(p);
}
__device__ __forceinline__ unsigned swz64(unsigned off) {   // 64B-row swizzle
    return off ^ ((off >> 3) & 0x30);
}
__device__ __forceinline__ void cp16(unsigned saddr, const void* g) {
    asm volatile("cp.async.cg.shared.global [%0], [%1], 16;\n" :: "r"(saddr), "l"(g));
}
__device__ __forceinline__ void ldsm4(unsigned* r, unsigned addr) {
    asm volatile("ldmatrix.sync.aligned.m8n8.x4.shared.b16 {%0,%1,%2,%3}, [%4];"
                 : "=r"(r[0]), "=r"(r[1]), "=r"(r[2]), "=r"(r[3]) : "r"(addr));
}
__device__ __forceinline__ void mma_s8(int* c, const unsigned* a, const unsigned* b) {
    asm volatile(
        "mma.sync.aligned.m16n8k32.row.col.s32.s8.s8.s32 "
        "{%0,%1,%2,%3}, {%4,%5,%6,%7}, {%8,%9}, {%0,%1,%2,%3};\n"
        : "+r"(c[0]), "+r"(c[1]), "+r"(c[2]), "+r"(c[3])
        : "r"(a[0]), "r"(a[1]), "r"(a[2]), "r"(a[3]), "r"(b[0]), "r"(b[1]));
}
__device__ __forceinline__ float wdeq_of(int idx) {
    return (float)fmax(d_wsum[idx] / (double)WELEMS, (double)EPSF);
}

__device__ __forceinline__ float blockMaxF(float v, float* red) {
    #pragma unroll
    for (int o = 16; o > 0; o >>= 1)
        v = fmaxf(v, __shfl_down_sync(0xffffffffu, v, o));
    int wid = threadIdx.x >> 5;
    if ((threadIdx.x & 31) == 0) red[wid] = v;
    __syncthreads();
    if (threadIdx.x < 8) {
        v = red[threadIdx.x];
        #pragma unroll
        for (int o = 4; o > 0; o >>= 1)
            v = fmaxf(v, __shfl_down_sync(0xffu, v, o));
        if (threadIdx.x == 0) red[0] = v;
    }
    __syncthreads();
    return red[0];
}

// ------------------------- small kernels -----------------------------------
__global__ void quantx_kernel(const float* __restrict__ x) {
    if (blockIdx.x == 0 && threadIdx.x < 3) d_wsum[threadIdx.x] = 0.0;
    __shared__ float red[8];
    const int t = blockIdx.x;
    const float4* xr = (const float4*)(x + (size_t)t * HDIM);
    float4 v[4];
    float m = 0.f;
    #pragma unroll
    for (int j = 0; j < 4; ++j) {
        v[j] = xr[threadIdx.x + j * 256];
        m = fmaxf(m, fmaxf(fmaxf(fabsf(v[j].x), fabsf(v[j].y)),
                           fmaxf(fabsf(v[j].z), fabsf(v[j].w))));
    }
    float amax = blockMaxF(m, red);
    float cmax = fmaxf(amax, EPSF);
    float sc = 127.0f / cmax;
    if (threadIdx.x == 0) d_xs[t] = cmax / 127.0f;
    char4* q4 = (char4*)(d_xq + (size_t)t * HDIM);
    #pragma unroll
    for (int j = 0; j < 4; ++j) {
        char4 c;
        c.x = (signed char)fminf(fmaxf(rintf(v[j].x * sc), -128.f), 127.f);
        c.y = (signed char)fminf(fmaxf(rintf(v[j].y * sc), -128.f), 127.f);
        c.z = (signed char)fminf(fmaxf(rintf(v[j].z * sc), -128.f), 127.f);
        c.w = (signed char)fminf(fmaxf(rintf(v[j].w * sc), -128.f), 127.f);
        q4[threadIdx.x + j * 256] = c;
    }
}

__global__ void absmean3_kernel(const float* __restrict__ w0,
                                const float* __restrict__ w1,
                                const float* __restrict__ w2) {
    const int idx = blockIdx.z;
    const float* w = (idx == 0) ? w0 : (idx == 1) ? w1 : w2;
    const size_t n4 = (size_t)WELEMS / 4;
    const float4* w4 = (const float4*)w;
    float a0 = 0.f, a1 = 0.f, a2 = 0.f, a3 = 0.f;
    for (size_t i = (size_t)blockIdx.x * blockDim.x + threadIdx.x; i < n4;
         i += (size_t)gridDim.x * blockDim.x) {
        float4 v = w4[i];
        a0 += fabsf(v.x); a1 += fabsf(v.y); a2 += fabsf(v.z); a3 += fabsf(v.w);
    }
    double local = ((double)a0 + (double)a1) + ((double)a2 + (double)a3);
    #pragma unroll
    for (int o = 16; o > 0; o >>= 1)
        local += __shfl_down_sync(0xffffffffu, local, o);
    __shared__ double red[8];
    int wid = threadIdx.x >> 5;
    if ((threadIdx.x & 31) == 0) red[wid] = local;
    __syncthreads();
    if (threadIdx.x < 8) {
        local = red[threadIdx.x];
        #pragma unroll
        for (int o = 4; o > 0; o >>= 1)
            local += __shfl_down_sync(0xffu, local, o);
        if (threadIdx.x == 0) atomicAdd(&d_wsum[idx], local);
    }
}

__global__ void quantw3_kernel(const float* __restrict__ w0,
                               const float* __restrict__ w1,
                               const float* __restrict__ w2) {
    const int idx = blockIdx.z;
    const float* w = (idx == 0) ? w0 : (idx == 1) ? w1 : w2;
    int8_t* q = (idx == 0) ? d_wgq : (idx == 1) ? d_wuq : d_wdq8;
    const float s = 1.0f / wdeq_of(idx);
    const size_t n4 = (size_t)WELEMS / 4;
    const float4* w4 = (const float4*)w;
    char4* q4 = (char4*)q;
    for (size_t i = (size_t)blockIdx.x * blockDim.x + threadIdx.x; i < n4;
         i += (size_t)gridDim.x * blockDim.x) {
        float4 v = w4[i];
        char4 c;
        c.x = (signed char)fminf(fmaxf(rintf(v.x * s), -1.f), 1.f);
        c.y = (signed char)fminf(fmaxf(rintf(v.y * s), -1.f), 1.f);
        c.z = (signed char)fminf(fmaxf(rintf(v.z * s), -1.f), 1.f);
        c.w = (signed char)fminf(fmaxf(rintf(v.w * s), -1.f), 1.f);
        q4[i] = c;
    }
}

__global__ void combine_quanth_kernel() {
    __shared__ float sh[IDIM];
    __shared__ float red[8];
    const int t = blockIdx.x;
    const float4* gr = (const float4*)(d_gbuf + (size_t)t * IDIM);
    const float4* ur = (const float4*)(d_ubuf + (size_t)t * IDIM);
    float4* sh4 = (float4*)sh;
    float m = 0.f;
    for (int i = threadIdx.x; i < IDIM / 4; i += 256) {
        float4 gv = gr[i], uv = ur[i], h;
        float r;
        r = fmaxf(gv.x, 0.f); h.x = r * r * uv.x;
        r = fmaxf(gv.y, 0.f); h.y = r * r * uv.y;
        r = fmaxf(gv.z, 0.f); h.z = r * r * uv.z;
        r = fmaxf(gv.w, 0.f); h.w = r * r * uv.w;
        sh4[i] = h;
        m = fmaxf(m, fmaxf(fmaxf(fabsf(h.x), fabsf(h.y)),
                           fmaxf(fabsf(h.z), fabsf(h.w))));
    }
    float amax = blockMaxF(m, red);
    float cmax = fmaxf(amax, EPSF);
    float sc = 127.0f / cmax;
    if (threadIdx.x == 0) d_hs[t] = cmax / 127.0f;
    __syncthreads();
    char4* q4 = (char4*)(d_hq + (size_t)t * IDIM);
    for (int i = threadIdx.x; i < IDIM / 4; i += 256) {
        float4 h = sh4[i];
        char4 c;
        c.x = (signed char)fminf(fmaxf(rintf(h.x * sc), -128.f), 127.f);
        c.y = (signed char)fminf(fmaxf(rintf(h.y * sc), -128.f), 127.f);
        c.z = (signed char)fminf(fmaxf(rintf(h.z * sc), -128.f), 127.f);
        c.w = (signed char)fminf(fmaxf(rintf(h.w * sc), -128.f), 127.f);
        q4[i] = c;
    }
}

// ------------------------- hybrid int8 GEMM --------------------------------
// C[M=4096, NDIM] = A[M, KDIM] (s8, K-major) x B[NDIM, KDIM]^T (s8)
// Per CTA: cols n0..n0+127 via IMMA (warps 8-15), n0+128..n0+255 via dp4a
// (warps 0-7, 8x8 outputs/thread, LDS.64). Stage = A 8KB + B 16KB = 24KB,
// 4 stages (96KB). BN_ALL=256 divides NDIM exactly (no guards).
template <int NDIM, int KDIM, int MODE>
__global__ __launch_bounds__(512, 1) void gemm_s8_kernel(float* __restrict__ out_arg) {
    constexpr int BK = 64;
    constexpr int STAGE_B = 24576;            // A 8KB + B 16KB
    constexpr int OFF_B = 8192;
    constexpr int KT = KDIM / BK;
    extern __shared__ int8_t smem[];
    const unsigned sbase = smem_u32(smem);

    const int8_t* A;
    const int8_t* Bm;
    float* outp;
    const float* ascale;
    int wsel;
    if (MODE == 0) {
        A = d_xq; ascale = d_xs;
        if (blockIdx.z == 0) { Bm = d_wgq; outp = d_gbuf; wsel = 0; }
        else                 { Bm = d_wuq; outp = d_ubuf; wsel = 1; }
    } else {
        A = d_hq; ascale = d_hs; Bm = d_wdq8; outp = out_arg; wsel = 2;
    }

    const int tid = threadIdx.x;
    const int m0 = blockIdx.y * 128, n0 = blockIdx.x * BN_ALL;
    const int wid = tid >> 5, lane = tid & 31;

    auto load_stage = [&](int kt) {
        if (kt < KT) {
            const unsigned sS = sbase + (kt & 3) * STAGE_B;
            const int k0 = kt * BK;
            {   // A: 128 rows x 4 segs = 512 units, one per thread
                int u = tid;
                cp16(sS + swz64((u >> 2) * 64 + (u & 3) * 16),
                     A + (size_t)(m0 + (u >> 2)) * KDIM + k0 + (u & 3) * 16);
            }
            #pragma unroll
            for (int i = 0; i < 2; ++i) {   // B: 256 rows x 4 segs = 1024 units
                int v = tid + i * 512;
                cp16(sS + OFF_B + swz64((v >> 2) * 64 + (v & 3) * 16),
                     Bm + (size_t)(n0 + (v >> 2)) * KDIM + k0 + (v & 3) * 16);
            }
        }
        asm volatile("cp.async.commit_group;\n");
    };

    load_stage(0); load_stage(1); load_stage(2);

    if (wid >= 8) {
        // ======== tensor warps (wid 8-15, HIGH priority): 128x128 IMMA =====
        const int wt = wid - 8;
        const int wm = (wt & 1) * 64, wn = (wt >> 1) * 32;
        const int arow = lane & 15, aks = (lane >> 4) * 16;
        const int brow = (lane & 7) + ((lane >> 4) & 1) * 8;
        const int bks  = ((lane >> 3) & 1) * 16;

        int acc[4][4][4];
        #pragma unroll
        for (int mi = 0; mi < 4; ++mi)
            #pragma unroll
            for (int ni = 0; ni < 4; ++ni)
                #pragma unroll
                for (int k = 0; k < 4; ++k) acc[mi][ni][k] = 0;

        for (int kt = 0; kt < KT; ++kt) {
            asm volatile("cp.async.wait_group 2;\n");
            __syncthreads();
            const unsigned sA = sbase + (kt & 3) * STAGE_B;
            const unsigned sB = sA + OFF_B;
            #pragma unroll
            for (int kk = 0; kk < BK; kk += 32) {
                unsigned a[4][4], b[2][4];
                #pragma unroll
                for (int mi = 0; mi < 4; ++mi)
                    ldsm4(a[mi], sA + swz64((wm + mi * 16 + arow) * 64 + kk + aks));
                #pragma unroll
                for (int np = 0; np < 2; ++np)
                    ldsm4(b[np], sB + swz64((wn + np * 16 + brow) * 64 + kk + bks));
                #pragma unroll
                for (int mi = 0; mi < 4; ++mi)
                    #pragma unroll
                    for (int ni = 0; ni < 4; ++ni)
                        mma_s8(acc[mi][ni], a[mi], &b[ni >> 1][(ni & 1) * 2]);
            }
            load_stage(kt + 3);
        }

        const float wsc = wdeq_of(wsel);
        const int g = lane >> 2, tg = lane & 3;
        #pragma unroll
        for (int mi = 0; mi < 4; ++mi) {
            int r0 = m0 + wm + mi * 16 + g;
            int r1 = r0 + 8;
            float s0 = ascale[r0] * wsc;
            float s1 = ascale[r1] * wsc;
            #pragma unroll
            for (int ni = 0; ni < 4; ++ni) {
                int c = n0 + wn + ni * 8 + tg * 2;
                float2 v0 = make_float2(acc[mi][ni][0] * s0, acc[mi][ni][1] * s0);
                float2 v1 = make_float2(acc[mi][ni][2] * s1, acc[mi][ni][3] * s1);
                *(float2*)(outp + (size_t)r0 * NDIM + c) = v0;
                *(float2*)(outp + (size_t)r1 * NDIM + c) = v1;
            }
        }
    } else {
        // ==== dp4a warps (wid 0-7): 128x128 cols, 8x8 per thread, LDS.64 ===
        const int wd = wid;
        const int wm2 = (wd & 1) * 64;            // row base (64-row half)
        const int wn2 = BN_T + (wd >> 1) * 32;    // col base (4 groups x 32)
        const int rg = lane >> 2;                 // 0..7 row offset
        const int cg = lane & 3;                  // 0..3 col offset

        int acc2[8][8];
        #pragma unroll
        for (int i = 0; i < 8; ++i)
            #pragma unroll
            for (int j = 0; j < 8; ++j) acc2[i][j] = 0;

        for (int kt = 0; kt < KT; ++kt) {
            asm volatile("cp.async.wait_group 2;\n");
            __syncthreads();
            const int8_t* sAp = smem + (kt & 3) * STAGE_B;
            const int8_t* sBp = sAp + OFF_B;
            #pragma unroll
            for (int kw8 = 0; kw8 < 8; ++kw8) {   // 8 bytes of K per step
                int2 a2[8], b2[8];
                #pragma unroll
                for (int i = 0; i < 8; ++i)
                    a2[i] = *(const int2*)(sAp +
                        swz64((wm2 + rg + 8 * i) * 64 + kw8 * 8));
                #pragma unroll
                for (int j = 0; j < 8; ++j)
                    b2[j] = *(const int2*)(sBp +
                        swz64((wn2 + cg + 4 * j) * 64 + kw8 * 8));
                #pragma unroll
                for (int i = 0; i < 8; ++i)
                    #pragma unroll
                    for (int j = 0; j < 8; ++j) {
                        int s = acc2[i][j];
                        s = __dp4a(a2[i].x, b2[j].x, s);
                        s = __dp4a(a2[i].y, b2[j].y, s);
                        acc2[i][j] = s;
                    }
            }
            load_stage(kt + 3);
        }

        const float wsc = wdeq_of(wsel);
        #pragma unroll
        for (int i = 0; i < 8; ++i) {
            int r = m0 + wm2 + rg + 8 * i;
            float s = ascale[r] * wsc;
            #pragma unroll
            for (int j = 0; j < 8; ++j) {
                int c = n0 + wn2 + cg + 4 * j;
                outp[(size_t)r * NDIM + c] = acc2[i][j] * s;
            }
        }
    }
}

// ------------------------- launch ------------------------------------------
extern "C" void kernel_launch(void* const* d_in, const int* in_sizes, int n_in,
                              void* d_out, int out_size) {
    const float* x      = (const float*)d_in[0];
    const float* w_gate = (const float*)d_in[1];
    const float* w_up   = (const float*)d_in[2];
    const float* w_down = (const float*)d_in[3];
    float* out = (float*)d_out;

    constexpr int GSMEM = 4 * 24576;   // 98304 B dynamic

    cudaFuncSetAttribute(gemm_s8_kernel<IDIM, HDIM, 0>,
                         cudaFuncAttributeMaxDynamicSharedMemorySize, GSMEM);
    cudaFuncSetAttribute(gemm_s8_kernel<HDIM, IDIM, 1>,
                         cudaFuncAttributeMaxDynamicSharedMemorySize, GSMEM);

    // 1: x quant (+ wsum zero)
    quantx_kernel<<<T_TOK, 256>>>(x);
    // 2: weight abs-mean
    absmean3_kernel<<<dim3(592, 1, 3), 256>>>(w_gate, w_up, w_down);
    // 3: weight ternary quant
    quantw3_kernel<<<dim3(592, 1, 3), 256>>>(w_gate, w_up, w_down);
    // 4: gate+up GEMM (hybrid)  <-- ncu capture lands here
    gemm_s8_kernel<IDIM, HDIM, 0>
        <<<dim3(IDIM / BN_ALL, T_TOK / 128, 2), 512, GSMEM>>>(nullptr);
    // 5: gating + h quant
    combine_quanth_kernel<<<T_TOK, 256>>>();
    // 6: down GEMM -> output (hybrid)
    gemm_s8_kernel<HDIM, IDIM, 1>
        <<<dim3(HDIM / BN_ALL, T_TOK / 128, 1), 512, GSMEM>>>(out);
}